// round 16
// baseline (speedup 1.0000x reference)
#include <cuda_runtime.h>
#include <cuda_fp16.h>
#include <math.h>
#include <stdint.h>

// ---------------------------------------------------------------- constants
#define BSZ   16384
#define INSZ  512
#define OUTSZ 512
#define ORD   10
#define KTOT  5632              // 512 silu + 10*512 scrambled chebyshev
#define BM    128
#define BN    128
#define BK    64
#define NKT   (KTOT / BK)       // 88
#define STAGES 3
#define STAGE_BYTES 32768       // A 16KB + B 16KB
#define SMEM_BYTES  (STAGES * STAGE_BYTES)   // 98304

// ---------------------------------------------------------------- scratch
__device__ __align__(16) __half g_a[(size_t)BSZ * KTOT];   // 176 MB
__device__ __align__(16) __half g_b[(size_t)OUTSZ * KTOT]; // 5.6 MB

// pack 4 floats -> uint2 of 4 halves via __half2 (no under-aligned punning)
__device__ __forceinline__ uint2 pack4h(float a, float b, float c, float d) {
    __half2 lo = __floats2half2_rn(a, b);
    __half2 hi = __floats2half2_rn(c, d);
    uint2 r;
    r.x = *reinterpret_cast<const uint32_t*>(&lo);
    r.y = *reinterpret_cast<const uint32_t*>(&hi);
    return r;
}

// --------------------------------------------------------- merged builder
// (R15 version, verbatim — proven at ~15us with L2 write-back overlap)
__global__ void build_all_kernel(const float* __restrict__ x,
                                 const float* __restrict__ base_w,
                                 const float* __restrict__ cheby_w) {
    int blk = blockIdx.x;
    int t   = threadIdx.x;                     // 0..127
    if (blk < BSZ) {
        int bb = blk;
        int i0 = t * 4;
        float4 xv4 = *(const float4*)&x[bb * INSZ + i0];
        float xv[4] = {xv4.x, xv4.y, xv4.z, xv4.w};

        float sl[4];
        #pragma unroll
        for (int q = 0; q < 4; q++) sl[q] = xv[q] / (1.0f + expf(-xv[q]));
        *(uint2*)&g_a[(size_t)bb * KTOT + i0] = pack4h(sl[0], sl[1], sl[2], sl[3]);

        float tm2[4] = {1.0f, 1.0f, 1.0f, 1.0f};
        float tm1[4] = {xv[0], xv[1], xv[2], xv[3]};
        #pragma unroll
        for (int o = 0; o < ORD; o++) {
            float tv[4];
            #pragma unroll
            for (int q = 0; q < 4; q++) {
                if (o == 0)      tv[q] = 1.0f;
                else if (o == 1) tv[q] = xv[q];
                else { float tt = 2.0f * xv[q] * tm1[q] - tm2[q];
                       tm2[q] = tm1[q]; tm1[q] = tt; tv[q] = tt; }
            }
            int m  = o * BSZ + bb;
            int b  = m / 10;
            int op = m - b * 10;
            *(uint2*)&g_a[(size_t)b * KTOT + INSZ + op * INSZ + i0] =
                pack4h(tv[0], tv[1], tv[2], tv[3]);
        }
    } else {
        int idx0 = (blk - BSZ) * 512 + t * 4;
        int out = idx0 / KTOT;
        int k   = idx0 - out * KTOT;
        float4 v4;
        if (k < INSZ) v4 = *(const float4*)&base_w[out * INSZ + k];
        else {
            v4 = *(const float4*)&cheby_w[out * (INSZ * ORD) + (k - INSZ)];
            v4.x *= 0.1f; v4.y *= 0.1f; v4.z *= 0.1f; v4.w *= 0.1f;
        }
        *(uint2*)&g_b[idx0] = pack4h(v4.x, v4.y, v4.z, v4.w);
    }
}

// --------------------------------------------------------- PTX primitives
__device__ __forceinline__ uint32_t smem_u32(const void* p) {
    uint32_t a;
    asm("{ .reg .u64 t; cvta.to.shared.u64 t, %1; cvt.u32.u64 %0, t; }" : "=r"(a) : "l"(p));
    return a;
}
__device__ __forceinline__ void cp16(uint32_t dst, const void* src) {
    asm volatile("cp.async.cg.shared.global [%0], [%1], 16;" :: "r"(dst), "l"(src));
}
#define LDSM_X4(d0, d1, d2, d3, addr)                                          \
    asm volatile("ldmatrix.sync.aligned.m8n8.x4.shared.b16 {%0,%1,%2,%3}, [%4];" \
                 : "=r"(d0), "=r"(d1), "=r"(d2), "=r"(d3) : "r"(addr))
#define HMMA(acc, a, b0, b1)                                                   \
    asm volatile("mma.sync.aligned.m16n8k16.row.col.f32.f16.f16.f32 "          \
                 "{%0,%1,%2,%3}, {%4,%5,%6,%7}, {%8,%9}, {%0,%1,%2,%3};"       \
                 : "+f"(acc[0]), "+f"(acc[1]), "+f"(acc[2]), "+f"(acc[3])      \
                 : "r"(a[0]), "r"(a[1]), "r"(a[2]), "r"(a[3]), "r"(b0), "r"(b1))

// ------------------------------------------------------------- HMMA GEMM
// R7 schedule with hand-CSE'd addressing:
//   r&7 == f_r&7 for every fragment row (row offsets are multiples of 8),
//   so the swizzle term ((2ks+f_k)^e)*16 is ONE scalar per ks shared by all
//   six LDSMs; row bases are 6 precomputed constants; stage bases rotate in
//   3 registers; global pointers advance by BK. Per-chunk ALU work ~4x lower
//   and LDSM address dep chains collapse to base+kterm.
__global__ void __launch_bounds__(256, 2) gemm_hmma_kernel(float* __restrict__ out) {
    extern __shared__ char smem[];
    uint32_t su = smem_u32(smem);
    int tid = threadIdx.x, lane = tid & 31, wid = tid >> 5;
    int mOff = (wid & 1) * 64;
    int nOff = (wid >> 1) * 32;
    int rowBase = blockIdx.y * BM;
    int colBase = blockIdx.x * BN;

    // loader mapping (2 threads/row, 4 chunks each); running global pointers
    int lr  = tid >> 1;
    int lc4 = (tid & 1) * 4;
    const __half* aq = g_a + (size_t)(rowBase + lr) * KTOT + lc4 * 8;
    const __half* bq = g_b + (size_t)(colBase + lr) * KTOT + lc4 * 8;
    // loader smem offsets (constant per thread)
    uint32_t woff[4];
    #pragma unroll
    for (int j = 0; j < 4; j++)
        woff[j] = (uint32_t)(lr * 128 + (((lc4 + j) ^ (lr & 7)) * 16));

    float acc[4][4][4];
    #pragma unroll
    for (int mi = 0; mi < 4; mi++)
        #pragma unroll
        for (int ni = 0; ni < 4; ni++)
            #pragma unroll
            for (int q = 0; q < 4; q++) acc[mi][ni][q] = 0.0f;

    // fragment addressing constants
    int f_r = lane & 15, f_k = lane >> 4;
    uint32_t e = (uint32_t)(f_r & 7);
    uint32_t kterm[4];
    #pragma unroll
    for (int ks = 0; ks < 4; ks++)
        kterm[ks] = (uint32_t)((((uint32_t)(ks * 2 + f_k)) ^ e) * 16);
    uint32_t baseA[4], baseB[2];
    #pragma unroll
    for (int mi = 0; mi < 4; mi++)
        baseA[mi] = (uint32_t)((mOff + mi * 16 + f_r) * 128);
    #pragma unroll
    for (int p = 0; p < 2; p++)
        baseB[p] = (uint32_t)((nOff + p * 16 + f_r) * 128) + 16384u;  // B after A

    uint32_t af[2][4][4];
    uint32_t bf[2][2][4];

    // produce one chunk into stage st (advances running pointers)
    auto produce = [&](uint32_t st) {
        #pragma unroll
        for (int j = 0; j < 4; j++) {
            cp16(st + woff[j],          aq + j * 8);
            cp16(st + 16384u + woff[j], bq + j * 8);
        }
        aq += BK; bq += BK;
        asm volatile("cp.async.commit_group;" ::: "memory");
    };
    auto load_frags = [&](uint32_t st, int ks, int bu) {
        uint32_t kk = kterm[ks];
        #pragma unroll
        for (int mi = 0; mi < 4; mi++) {
            uint32_t ad = st + baseA[mi] + kk;
            LDSM_X4(af[bu][mi][0], af[bu][mi][1], af[bu][mi][2], af[bu][mi][3], ad);
        }
        #pragma unroll
        for (int p = 0; p < 2; p++) {
            uint32_t bd = st + baseB[p] + kk;
            LDSM_X4(bf[bu][p][0], bf[bu][p][1], bf[bu][p][2], bf[bu][p][3], bd);
        }
    };
    auto mma_step = [&](int bu) {
        #pragma unroll
        for (int mi = 0; mi < 4; mi++)
            #pragma unroll
            for (int p = 0; p < 2; p++) {
                HMMA(acc[mi][2 * p],     af[bu][mi], bf[bu][p][0], bf[bu][p][2]);
                HMMA(acc[mi][2 * p + 1], af[bu][mi], bf[bu][p][1], bf[bu][p][3]);
            }
    };

    // prologue: chunks 0, 1 into stages 0, 1
    produce(su);
    produce(su + STAGE_BYTES);

    asm volatile("cp.async.wait_group 1;" ::: "memory");
    __syncthreads();
    load_frags(su, 0, 0);

    // rotating stage bases: cur = stage(kt), nxt = stage(kt+1), prd = stage(kt+2)
    uint32_t cur = su, nxt = su + STAGE_BYTES, prd = su + 2 * STAGE_BYTES;

    for (int kt = 0; kt < NKT; kt++) {
        #pragma unroll
        for (int ks = 0; ks < 3; ks++) {
            load_frags(cur, ks + 1, (ks & 1) ^ 1);   // prefetch ks+1 frags
            mma_step(ks & 1);                         // MMA ks
        }

        // ---- transition (hidden under the trailing ks=3 MMAs) ----
        if (kt + 1 < NKT) {
            asm volatile("cp.async.wait_group 0;" ::: "memory");
            __syncthreads();
            load_frags(nxt, 0, 0);                    // next chunk ks0 -> buf 0
            if (kt + 2 < NKT) produce(prd);           // issue chunk kt+2
        }

        mma_step(1);                                  // MMA ks=3 (buf 1)

        uint32_t t = cur; cur = nxt; nxt = prd; prd = t;   // rotate stages
    }

    // epilogue: C fragment layout -> float2 global stores
    int gid = lane >> 2, tig = lane & 3;
    #pragma unroll
    for (int mi = 0; mi < 4; mi++) {
        int r0 = rowBase + mOff + mi * 16 + gid;
        #pragma unroll
        for (int ni = 0; ni < 4; ni++) {
            int cc = colBase + nOff + ni * 8 + tig * 2;
            float2 v0 = make_float2(acc[mi][ni][0], acc[mi][ni][1]);
            float2 v1 = make_float2(acc[mi][ni][2], acc[mi][ni][3]);
            *(float2*)&out[(size_t)r0 * OUTSZ + cc]       = v0;
            *(float2*)&out[(size_t)(r0 + 8) * OUTSZ + cc] = v1;
        }
    }
}

// ----------------------------------------------------------------- launch
extern "C" void kernel_launch(void* const* d_in, const int* in_sizes, int n_in,
                              void* d_out, int out_size) {
    const float* x  = (const float*)d_in[0];   // (16384, 512)
    const float* bw = (const float*)d_in[1];   // (512, 512)
    const float* cw = (const float*)d_in[2];   // (512, 512, 10)
    float* out = (float*)d_out;

    cudaFuncSetAttribute(gemm_hmma_kernel,
                         cudaFuncAttributeMaxDynamicSharedMemorySize, SMEM_BYTES);

    build_all_kernel<<<BSZ + OUTSZ * KTOT / 512, 128>>>(x, bw, cw);

    dim3 grid(OUTSZ / BN, BSZ / BM);   // (4, 128)
    gemm_hmma_kernel<<<grid, 256, SMEM_BYTES>>>(out);
}

// round 17
// speedup vs baseline: 1.0968x; 1.0968x over previous
#include <cuda_runtime.h>
#include <cuda_fp16.h>
#include <math.h>
#include <stdint.h>

// ---------------------------------------------------------------- constants
#define BSZ   16384
#define INSZ  512
#define OUTSZ 512
#define ORD   10
#define KTOT  5632              // 512 silu + 10*512 scrambled chebyshev
#define BM    128
#define BN    128
#define BK    64
#define NKT   (KTOT / BK)       // 88
#define STAGES 3
#define STAGE_BYTES 32768       // A 16KB + B 16KB
#define SMEM_BYTES  (STAGES * STAGE_BYTES)   // 98304

// ---------------------------------------------------------------- scratch
__device__ __align__(16) __half g_a[(size_t)BSZ * KTOT];   // 176 MB
__device__ __align__(16) __half g_b[(size_t)OUTSZ * KTOT]; // 5.6 MB

// pack 4 floats -> uint2 of 4 halves via __half2 (no under-aligned punning)
__device__ __forceinline__ uint2 pack4h(float a, float b, float c, float d) {
    __half2 lo = __floats2half2_rn(a, b);
    __half2 hi = __floats2half2_rn(c, d);
    uint2 r;
    r.x = *reinterpret_cast<const uint32_t*>(&lo);   // __half2 is 4-aligned
    r.y = *reinterpret_cast<const uint32_t*>(&hi);
    return r;
}

// --------------------------------------------------------- merged builder
// Vectorized: 128 threads/block, each thread owns 4 consecutive elements
// (float4 load, uint2 = 4xhalf store).
// blocks [0, BSZ):        Act row bb = blk (silu + 10 scrambled cheby rows)
// blocks [BSZ, BSZ+5632): Wc, 512 elements per block
__global__ void build_all_kernel(const float* __restrict__ x,
                                 const float* __restrict__ base_w,
                                 const float* __restrict__ cheby_w) {
    int blk = blockIdx.x;
    int t   = threadIdx.x;                     // 0..127
    if (blk < BSZ) {
        int bb = blk;
        int i0 = t * 4;
        float4 xv4 = *(const float4*)&x[bb * INSZ + i0];
        float xv[4] = {xv4.x, xv4.y, xv4.z, xv4.w};

        // silu
        float sl[4];
        #pragma unroll
        for (int q = 0; q < 4; q++) sl[q] = xv[q] / (1.0f + expf(-xv[q]));
        *(uint2*)&g_a[(size_t)bb * KTOT + i0] = pack4h(sl[0], sl[1], sl[2], sl[3]);

        // chebyshev recurrence on 4 lanes; scatter per order:
        // Act[b, 512+o'*512+i] = T_o(x[bb,i]), m = o*16384+bb, b = m/10, o' = m%10
        float tm2[4] = {1.0f, 1.0f, 1.0f, 1.0f};
        float tm1[4] = {xv[0], xv[1], xv[2], xv[3]};
        #pragma unroll
        for (int o = 0; o < ORD; o++) {
            float tv[4];
            #pragma unroll
            for (int q = 0; q < 4; q++) {
                if (o == 0)      tv[q] = 1.0f;
                else if (o == 1) tv[q] = xv[q];
                else { float tt = 2.0f * xv[q] * tm1[q] - tm2[q];
                       tm2[q] = tm1[q]; tm1[q] = tt; tv[q] = tt; }
            }
            int m  = o * BSZ + bb;
            int b  = m / 10;
            int op = m - b * 10;
            *(uint2*)&g_a[(size_t)b * KTOT + INSZ + op * INSZ + i0] =
                pack4h(tv[0], tv[1], tv[2], tv[3]);
        }
    } else {
        // Wc: blk-BSZ in [0,5632), 512 elems per block, 4 per thread
        int idx0 = (blk - BSZ) * 512 + t * 4;
        int out = idx0 / KTOT;
        int k   = idx0 - out * KTOT;           // 4-aligned; branch uniform per group
        float4 v4;
        if (k < INSZ) v4 = *(const float4*)&base_w[out * INSZ + k];
        else {
            v4 = *(const float4*)&cheby_w[out * (INSZ * ORD) + (k - INSZ)];
            v4.x *= 0.1f; v4.y *= 0.1f; v4.z *= 0.1f; v4.w *= 0.1f;
        }
        *(uint2*)&g_b[idx0] = pack4h(v4.x, v4.y, v4.z, v4.w);
    }
}

// --------------------------------------------------------- PTX primitives
__device__ __forceinline__ uint32_t smem_u32(const void* p) {
    uint32_t a;
    asm("{ .reg .u64 t; cvta.to.shared.u64 t, %1; cvt.u32.u64 %0, t; }" : "=r"(a) : "l"(p));
    return a;
}
__device__ __forceinline__ void cp16(uint32_t dst, const void* src) {
    asm volatile("cp.async.cg.shared.global [%0], [%1], 16;" :: "r"(dst), "l"(src));
}
#define LDSM_X4(d0, d1, d2, d3, addr)                                          \
    asm volatile("ldmatrix.sync.aligned.m8n8.x4.shared.b16 {%0,%1,%2,%3}, [%4];" \
                 : "=r"(d0), "=r"(d1), "=r"(d2), "=r"(d3) : "r"(addr))
#define HMMA(acc, a, b0, b1)                                                   \
    asm volatile("mma.sync.aligned.m16n8k16.row.col.f32.f16.f16.f32 "          \
                 "{%0,%1,%2,%3}, {%4,%5,%6,%7}, {%8,%9}, {%0,%1,%2,%3};"       \
                 : "+f"(acc[0]), "+f"(acc[1]), "+f"(acc[2]), "+f"(acc[3])      \
                 : "r"(a[0]), "r"(a[1]), "r"(a[2]), "r"(a[3]), "r"(b0), "r"(b1))

// ------------------------------------------------------------- HMMA GEMM
// Best measured configuration (R7/R15): CTA 128x128, BK=64, 3-stage cp.async
// pipeline, 8 warps (2m x 4n), warp tile 64x32; chunk transition placed
// between ks=2 and ks=3 so the trailing 16 HMMAs hide barrier skew + LDSM
// latency. Verified faster than: frag double-buffering (R6), 64x64 warp
// tiles (R8), 64x64 CTAs (R10), mbarrier pipeline (R12), manual CSE (R16).
__global__ void __launch_bounds__(256, 2) gemm_hmma_kernel(float* __restrict__ out) {
    extern __shared__ char smem[];
    uint32_t su = smem_u32(smem);
    int tid = threadIdx.x, lane = tid & 31, wid = tid >> 5;
    int mOff = (wid & 1) * 64;
    int nOff = (wid >> 1) * 32;
    int rowBase = blockIdx.y * BM;
    int colBase = blockIdx.x * BN;

    const __half* Ag = g_a + (size_t)rowBase * KTOT;
    const __half* Bg = g_b + (size_t)colBase * KTOT;

    int lr  = tid >> 1;
    int lc4 = (tid & 1) * 4;
    const __half* agb = Ag + (size_t)lr * KTOT + lc4 * 8;
    const __half* bgb = Bg + (size_t)lr * KTOT + lc4 * 8;

    float acc[4][4][4];
    #pragma unroll
    for (int mi = 0; mi < 4; mi++)
        #pragma unroll
        for (int ni = 0; ni < 4; ni++)
            #pragma unroll
            for (int q = 0; q < 4; q++) acc[mi][ni][q] = 0.0f;

    int f_r = lane & 15, f_k = lane >> 4;

    uint32_t af[2][4][4];
    uint32_t bf[2][2][4];

    #pragma unroll
    for (int p = 0; p < 2; p++) {
        uint32_t sa = su + p * STAGE_BYTES, sb = sa + 16384;
        #pragma unroll
        for (int j = 0; j < 4; j++) {
            int c = lc4 + j;
            uint32_t off = (uint32_t)(lr * 128 + ((c ^ (lr & 7)) * 16));
            cp16(sa + off, agb + p * BK + j * 8);
            cp16(sb + off, bgb + p * BK + j * 8);
        }
        asm volatile("cp.async.commit_group;" ::: "memory");
    }

    auto load_frags = [&](uint32_t sa, uint32_t sb, int ks, int bu) {
        int c = ks * 2 + f_k;
        #pragma unroll
        for (int mi = 0; mi < 4; mi++) {
            int r = mOff + mi * 16 + f_r;
            uint32_t ad = sa + (uint32_t)(r * 128 + ((c ^ (r & 7)) * 16));
            LDSM_X4(af[bu][mi][0], af[bu][mi][1], af[bu][mi][2], af[bu][mi][3], ad);
        }
        #pragma unroll
        for (int p = 0; p < 2; p++) {
            int r = nOff + p * 16 + f_r;
            uint32_t bd = sb + (uint32_t)(r * 128 + ((c ^ (r & 7)) * 16));
            LDSM_X4(bf[bu][p][0], bf[bu][p][1], bf[bu][p][2], bf[bu][p][3], bd);
        }
    };
    auto mma_step = [&](int bu) {
        #pragma unroll
        for (int mi = 0; mi < 4; mi++)
            #pragma unroll
            for (int p = 0; p < 2; p++) {
                HMMA(acc[mi][2 * p],     af[bu][mi], bf[bu][p][0], bf[bu][p][2]);
                HMMA(acc[mi][2 * p + 1], af[bu][mi], bf[bu][p][1], bf[bu][p][3]);
            }
    };

    asm volatile("cp.async.wait_group 1;" ::: "memory");
    __syncthreads();
    load_frags(su, su + 16384, 0, 0);

    for (int kt = 0; kt < NKT; kt++) {
        uint32_t sa = su + (kt % STAGES) * STAGE_BYTES, sb = sa + 16384;

        #pragma unroll
        for (int ks = 0; ks < 3; ks++) {
            load_frags(sa, sb, ks + 1, (ks & 1) ^ 1);
            mma_step(ks & 1);
        }

        if (kt + 1 < NKT) {
            asm volatile("cp.async.wait_group 0;" ::: "memory");
            __syncthreads();
            uint32_t na = su + ((kt + 1) % STAGES) * STAGE_BYTES, nb = na + 16384;
            load_frags(na, nb, 0, 0);
            if (kt + 2 < NKT) {
                uint32_t pa = su + ((kt + 2) % STAGES) * STAGE_BYTES, pb = pa + 16384;
                #pragma unroll
                for (int j = 0; j < 4; j++) {
                    int c = lc4 + j;
                    uint32_t off = (uint32_t)(lr * 128 + ((c ^ (lr & 7)) * 16));
                    cp16(pa + off, agb + (size_t)(kt + 2) * BK + j * 8);
                    cp16(pb + off, bgb + (size_t)(kt + 2) * BK + j * 8);
                }
                asm volatile("cp.async.commit_group;" ::: "memory");
            }
        }

        mma_step(1);
    }

    int gid = lane >> 2, tig = lane & 3;
    #pragma unroll
    for (int mi = 0; mi < 4; mi++) {
        int r0 = rowBase + mOff + mi * 16 + gid;
        #pragma unroll
        for (int ni = 0; ni < 4; ni++) {
            int cc = colBase + nOff + ni * 8 + tig * 2;
            float2 v0 = make_float2(acc[mi][ni][0], acc[mi][ni][1]);
            float2 v1 = make_float2(acc[mi][ni][2], acc[mi][ni][3]);
            *(float2*)&out[(size_t)r0 * OUTSZ + cc]       = v0;
            *(float2*)&out[(size_t)(r0 + 8) * OUTSZ + cc] = v1;
        }
    }
}

// ----------------------------------------------------------------- launch
extern "C" void kernel_launch(void* const* d_in, const int* in_sizes, int n_in,
                              void* d_out, int out_size) {
    const float* x  = (const float*)d_in[0];   // (16384, 512)
    const float* bw = (const float*)d_in[1];   // (512, 512)
    const float* cw = (const float*)d_in[2];   // (512, 512, 10)
    float* out = (float*)d_out;

    cudaFuncSetAttribute(gemm_hmma_kernel,
                         cudaFuncAttributeMaxDynamicSharedMemorySize, SMEM_BYTES);

    // 16384 Act blocks + 5632 Wc blocks, 128 threads each
    build_all_kernel<<<BSZ + OUTSZ * KTOT / 512, 128>>>(x, bw, cw);

    dim3 grid(OUTSZ / BN, BSZ / BM);   // (4, 128)
    gemm_hmma_kernel<<<grid, 256, SMEM_BYTES>>>(out);
}